// round 2
// baseline (speedup 1.0000x reference)
#include <cuda_runtime.h>
#include <cstdint>

#define B_DIM 16
#define P_DIM 4096
#define T_DIM 1024
#define PCHUNK 512
#define NTHREADS 256
#define TPT 4   // targets per thread: 256 threads * 4 = 1024 = T_DIM

// Scratch (no allocations allowed)
__device__ unsigned long long g_best[B_DIM * T_DIM];
__device__ unsigned char g_hits[B_DIM * P_DIM];

__global__ void init_kernel() {
    int i = blockIdx.x * blockDim.x + threadIdx.x;  // 0..16383
    g_best[i] = ~0ull;
    ((unsigned int*)g_hits)[i] = 0u;  // 16384 * 4 = 65536 bytes
}

__global__ void score_kernel(const float* __restrict__ pred,
                             const float* __restrict__ gt) {
    const int b  = blockIdx.x;
    const int p0 = blockIdx.y * PCHUNK;

    __shared__ float s_cls[PCHUNK];
    __shared__ float s_x[PCHUNK];
    __shared__ float s_y[PCHUNK];

    const float* pb = pred + (size_t)b * P_DIM * 3;
    for (int i = threadIdx.x; i < PCHUNK; i += NTHREADS) {
        const float* e = pb + (size_t)(p0 + i) * 3;
        s_cls[i] = e[0];
        s_x[i]   = e[1];
        s_y[i]   = e[2];
    }
    __syncthreads();

    const float* gb = gt + (size_t)b * T_DIM * 3;
    float tcls[TPT], tx[TPT], ty[TPT], bd[TPT];
    int   bj[TPT];
#pragma unroll
    for (int k = 0; k < TPT; k++) {
        int t = threadIdx.x + k * NTHREADS;
        const float* e = gb + (size_t)t * 3;
        tcls[k] = e[0];
        tx[k]   = e[1];
        ty[k]   = e[2];
        bd[k]   = __int_as_float(0x7f800000);  // +inf
        bj[k]   = -1;
    }

#pragma unroll 4
    for (int j = 0; j < PCHUNK; j++) {
        const float c = s_cls[j];
        const float x = s_x[j];
        const float y = s_y[j];
#pragma unroll
        for (int k = 0; k < TPT; k++) {
            float dx = x - tx[k];
            float dy = y - ty[k];
            float d2 = fmaf(dx, dx, dy * dy);
            // valid: class match AND within radius (d2 <= 25); keep FIRST min (strict <)
            bool ok = (c == tcls[k]) & (d2 <= 25.0f) & (d2 < bd[k]);
            if (ok) { bd[k] = d2; bj[k] = j; }
        }
    }

#pragma unroll
    for (int k = 0; k < TPT; k++) {
        if (bj[k] >= 0) {
            int t = threadIdx.x + k * NTHREADS;
            // key: (d2 bits << 32) | global_p  -> min gives smallest d2, tie -> smallest p
            unsigned long long key =
                ((unsigned long long)__float_as_uint(bd[k]) << 32) |
                (unsigned int)(p0 + bj[k]);
            atomicMin(&g_best[b * T_DIM + t], key);
        }
    }
}

__global__ void scatter_kernel() {
    int i = blockIdx.x * blockDim.x + threadIdx.x;  // 0..B*T-1
    unsigned long long v = g_best[i];
    if (v != ~0ull) {
        int b = i / T_DIM;
        int p = (int)(v & 0xFFFFFFFFu);
        g_hits[b * P_DIM + p] = 1;  // idempotent
    }
}

__global__ void reduce_kernel(float* __restrict__ out) {
    __shared__ int warp_sums[32];
    int sum = 0;
    const unsigned int* h = (const unsigned int*)g_hits;
    for (int i = threadIdx.x; i < (B_DIM * P_DIM) / 4; i += 1024)
        sum += __popc(h[i]);  // bytes are 0/1 -> only bit0 of each byte set

#pragma unroll
    for (int o = 16; o; o >>= 1) sum += __shfl_down_sync(0xFFFFFFFFu, sum, o);
    if ((threadIdx.x & 31) == 0) warp_sums[threadIdx.x >> 5] = sum;
    __syncthreads();
    if (threadIdx.x < 32) {
        int s = warp_sums[threadIdx.x];
#pragma unroll
        for (int o = 16; o; o >>= 1) s += __shfl_down_sync(0xFFFFFFFFu, s, o);
        if (threadIdx.x == 0) {
            float tp  = (float)s;
            float fp  = (float)(B_DIM * P_DIM) - tp;
            float fn  = (float)(B_DIM * T_DIM) - tp;
            float eps = 1e-6f;
            float precision = (tp + eps) / (tp + eps + fp + eps);
            float recall    = (tp + eps) / (tp + fn + eps);
            float f1 = 2.0f * precision * recall / (precision + recall);
            out[0] = 1.0f - f1;
        }
    }
}

extern "C" void kernel_launch(void* const* d_in, const int* in_sizes, int n_in,
                              void* d_out, int out_size) {
    // pred: 16*4096*3 = 196608 elems; gt: 16*1024*3 = 49152 elems
    const float* pred = (const float*)d_in[0];
    const float* gt   = (const float*)d_in[1];
    if (n_in >= 2 && in_sizes[0] == B_DIM * T_DIM * 3) {  // swapped order guard
        pred = (const float*)d_in[1];
        gt   = (const float*)d_in[0];
    }
    float* out = (float*)d_out;

    init_kernel<<<64, 256>>>();
    dim3 grid(B_DIM, P_DIM / PCHUNK);           // 16 x 8 = 128 blocks
    score_kernel<<<grid, NTHREADS>>>(pred, gt);
    scatter_kernel<<<64, 256>>>();
    reduce_kernel<<<1, 1024>>>(out);
}

// round 3
// speedup vs baseline: 1.6633x; 1.6633x over previous
#include <cuda_runtime.h>
#include <cstdint>

#define B_DIM 16
#define P_DIM 4096
#define T_DIM 1024
#define PCHUNK 512
#define NT 512          // threads in score kernel
#define TPT 2           // targets per thread: 512*2 = 1024

// Zero-initialized scratch. finalize_kernel restores everything to zero each
// call, so no init kernel is needed (graph replays start clean).
__device__ unsigned long long g_best[B_DIM * T_DIM];   // holds ~key, 0 = empty
__device__ unsigned int g_tp;
__device__ unsigned int g_done;

// key = (d2_truncated_bits << 32) | global_p ; stored as ~key with atomicMax
// => effectively min over (d2, p): smallest d2, tie -> smallest p (first argmax).

__global__ void score_kernel(const float* __restrict__ pred,
                             const float* __restrict__ gt) {
    const int b  = blockIdx.x;
    const int p0 = blockIdx.y * PCHUNK;

    __shared__ float2 s_pk[PCHUNK];  // (x + 128*cls, y)

    // Stage 512 preds, one per thread, folding class into x.
    {
        const float* e = pred + ((size_t)b * P_DIM + p0 + threadIdx.x) * 3;
        float c = e[0], x = e[1], y = e[2];
        s_pk[threadIdx.x] = make_float2(fmaf(c, 128.0f, x), y);
    }
    __syncthreads();

    const float* gb = gt + (size_t)b * T_DIM * 3;
    float txk[TPT], tyk[TPT];
    int best[TPT];
#pragma unroll
    for (int k = 0; k < TPT; k++) {
        const float* e = gb + (size_t)(threadIdx.x + k * NT) * 3;
        float c = e[0];
        txk[k] = fmaf(c, 128.0f, e[1]);
        tyk[k] = e[2];
        best[k] = 0x7F800000;  // +inf bits; all real d2 compare below as ints
    }

    const float4* s4 = (const float4*)s_pk;  // 2 preds per float4
#pragma unroll 4
    for (int j2 = 0; j2 < PCHUNK / 2; j2++) {
        float4 q = s4[j2];
#pragma unroll
        for (int k = 0; k < TPT; k++) {
            float dx = q.x - txk[k];
            float dy = q.y - tyk[k];
            float d2 = fmaf(dx, dx, dy * dy);
            int m = (__float_as_int(d2) & 0xFFFFFE00) | (2 * j2);
            best[k] = min(best[k], m);      // IMNMX: positive floats order as ints
            dx = q.z - txk[k];
            dy = q.w - tyk[k];
            d2 = fmaf(dx, dx, dy * dy);
            m = (__float_as_int(d2) & 0xFFFFFE00) | (2 * j2 + 1);
            best[k] = min(best[k], m);
        }
    }

#pragma unroll
    for (int k = 0; k < TPT; k++) {
        int d2part = best[k] & 0xFFFFFE00;
        if (d2part <= 0x41C80000) {  // d2 <= 25.0f  (class folded in)
            unsigned p = (unsigned)(p0 + (best[k] & 511));
            unsigned long long key =
                ((unsigned long long)(unsigned)d2part << 32) | p;
            atomicMax(&g_best[b * T_DIM + threadIdx.x + k * NT], ~key);
        }
    }
}

// One block per batch: dedup best-preds in a 4096-bit smem mask, count new
// bits, last block computes f1 and resets all scratch state.
__global__ void finalize_kernel(float* __restrict__ out) {
    __shared__ unsigned s_mask[P_DIM / 32];  // 128 words
    const int b = blockIdx.x;
    const int t = threadIdx.x;

    if (t < P_DIM / 32) s_mask[t] = 0u;
    __syncthreads();

    const int idx = b * T_DIM + t;
    unsigned long long v = g_best[idx];
    g_best[idx] = 0ull;  // restore for next replay

    int newbit = 0;
    if (v != 0ull) {
        unsigned p = (unsigned)(~v) & (P_DIM - 1);  // low 32 of key = global p
        unsigned bit = 1u << (p & 31u);
        unsigned old = atomicOr(&s_mask[p >> 5], bit);
        newbit = (old & bit) ? 0 : 1;
    }

    int cnt = __syncthreads_count(newbit);

    if (t == 0) {
        atomicAdd(&g_tp, (unsigned)cnt);
        __threadfence();
        unsigned ticket = atomicAdd(&g_done, 1u);
        if (ticket == B_DIM - 1) {
            float tp = (float)atomicAdd(&g_tp, 0u);
            float fp = (float)(B_DIM * P_DIM) - tp;
            float fn = (float)(B_DIM * T_DIM) - tp;
            const float eps = 1e-6f;
            float precision = (tp + eps) / (tp + eps + fp + eps);
            float recall    = (tp + eps) / (tp + fn + eps);
            float f1 = 2.0f * precision * recall / (precision + recall);
            out[0] = 1.0f - f1;
            g_tp = 0u;    // restore for next replay
            g_done = 0u;
        }
    }
}

extern "C" void kernel_launch(void* const* d_in, const int* in_sizes, int n_in,
                              void* d_out, int out_size) {
    const float* pred = (const float*)d_in[0];
    const float* gt   = (const float*)d_in[1];
    if (n_in >= 2 && in_sizes[0] == B_DIM * T_DIM * 3) {  // swapped-order guard
        pred = (const float*)d_in[1];
        gt   = (const float*)d_in[0];
    }
    float* out = (float*)d_out;

    dim3 grid(B_DIM, P_DIM / PCHUNK);  // 16 x 8 = 128 blocks
    score_kernel<<<grid, NT>>>(pred, gt);
    finalize_kernel<<<B_DIM, T_DIM>>>(out);
}